// round 2
// baseline (speedup 1.0000x reference)
#include <cuda_runtime.h>
#include <math.h>

#define T_ 24
#define B_ 64
#define I_ 128
#define H_ 256
#define R_ 64
#define HR 320
#define HH (H_*H_)

// -------- device scratch (no allocations allowed) --------
__device__ float g_Wx[T_*B_*HR];      // precomputed LN(x@x2h_w.T + b) for all t
__device__ float g_h[2*B_*H_];        // ping-pong h
__device__ float g_te[2*B_*H_];       // ping-pong trace_e
__device__ float g_z[B_*H_];          // einsum(ra*dU, h) for the *next* step
__device__ float g_mod[B_*H_];        // mod vector for current step
__device__ float g_ra[HH];
__device__ float g_sE[HH];
__device__ float g_sU[HH];
__device__ float g_hi[HH];
__device__ float g_lo[HH];
__device__ float g_sv[H_];

__device__ __forceinline__ float sigmoidf(float x) { return 1.f / (1.f + expf(-x)); }

// -------- one-time constants --------
__global__ void k_consts(const float* __restrict__ alpha,
                         const float* __restrict__ tauU,
                         const float* __restrict__ tauE,
                         const float* __restrict__ h2h_w,
                         const float* __restrict__ tau_v) {
    int idx = blockIdx.x * blockDim.x + threadIdx.x;
    if (idx < HH) {
        float ra = fmaxf(alpha[idx], 0.f);
        g_ra[idx] = ra;
        g_sU[idx] = sigmoidf(tauU[idx]);
        g_sE[idx] = sigmoidf(tauE[idx]);
        // W_hh = h2h_w[:H,:] ; linear index identical for i<H
        float w = h2h_w[idx];
        float denom = ra + 1e-8f;
        g_hi[idx] =  fmaxf(1.0f - w, 0.f) / denom;
        g_lo[idx] = -fmaxf(1.0f + w, 0.f) / denom;
    }
    if (idx < H_) g_sv[idx] = sigmoidf(tau_v[idx]);
}

// -------- Wx for all timesteps: LN(x_t @ x2h_w.T + x2h_b) --------
// grid = T*B blocks, HR threads
__global__ void k_wx(const float* __restrict__ x,
                     const float* __restrict__ w,
                     const float* __restrict__ bias,
                     const float* __restrict__ lng,
                     const float* __restrict__ lnb) {
    int tb = blockIdx.x;
    int k = threadIdx.x;               // 0..319
    __shared__ float sx[I_];
    __shared__ float red[20];
    const float* xr = x + tb * I_;
    if (k < I_) sx[k] = xr[k];
    __syncthreads();

    float acc = bias[k];
    const float4* wr = (const float4*)(w + k * I_);
#pragma unroll
    for (int m = 0; m < I_/4; m++) {
        float4 wv = wr[m];
        acc += wv.x*sx[4*m] + wv.y*sx[4*m+1] + wv.z*sx[4*m+2] + wv.w*sx[4*m+3];
    }
    // block LN over HR values
    float s = acc, s2 = acc*acc;
#pragma unroll
    for (int o = 16; o > 0; o >>= 1) {
        s  += __shfl_xor_sync(0xffffffffu, s,  o);
        s2 += __shfl_xor_sync(0xffffffffu, s2, o);
    }
    int wid = k >> 5, lane = k & 31;
    if (lane == 0) { red[wid] = s; red[10 + wid] = s2; }
    __syncthreads();
    if (wid == 0) {
        float a  = (lane < 10) ? red[lane] : 0.f;
        float b2 = (lane < 10) ? red[10 + lane] : 0.f;
#pragma unroll
        for (int o = 16; o > 0; o >>= 1) {
            a  += __shfl_xor_sync(0xffffffffu, a,  o);
            b2 += __shfl_xor_sync(0xffffffffu, b2, o);
        }
        if (lane == 0) { red[0] = a; red[10] = b2; }
    }
    __syncthreads();
    float mu  = red[0] * (1.f/HR);
    float var = red[10] * (1.f/HR) - mu*mu;
    float inv = rsqrtf(var + 1e-5f);
    g_Wx[tb*HR + k] = (acc - mu) * inv * lng[k] + lnb[k];
}

// -------- initial einsum z0 = einsum('bij,bj->bi', ra*dU0, h0) --------
// grid = (8 b-groups, H) ; block = H threads (thread = j)
__global__ void k_zinit(const float* __restrict__ dU0, const float* __restrict__ h0) {
    int i  = blockIdx.y;
    int b0 = blockIdx.x * 8;
    int j  = threadIdx.x;
    float ra = g_ra[i*H_ + j];
    float part[8];
#pragma unroll
    for (int bb = 0; bb < 8; bb++) {
        int b = b0 + bb;
        part[bb] = ra * dU0[(b*H_ + i)*H_ + j] * h0[b*H_ + j];
    }
    __shared__ float sp[8][H_];
#pragma unroll
    for (int bb = 0; bb < 8; bb++) sp[bb][j] = part[bb];
    __syncthreads();
    int wid = j >> 5, lane = j & 31;
    float s = 0.f;
#pragma unroll
    for (int m = 0; m < 8; m++) s += sp[wid][lane + 32*m];
#pragma unroll
    for (int o = 16; o > 0; o >>= 1) s += __shfl_xor_sync(0xffffffffu, s, o);
    if (lane == 0) g_z[(b0 + wid)*H_ + i] = s;
}

// -------- per-step small kernel: Wh GEMM + LN + v/h/te update + mod --------
// grid = B blocks, HR threads
__global__ void k_step_small(int t,
                             const float* __restrict__ h_old,
                             const float* __restrict__ te_old,
                             float* __restrict__ h_new,
                             float* __restrict__ te_new,
                             const float* __restrict__ h2h_w,
                             const float* __restrict__ h2h_b,
                             const float* __restrict__ lng,
                             const float* __restrict__ lnb,
                             const float* __restrict__ mod2h,
                             float* __restrict__ v,
                             float* __restrict__ out_seq) {
    int b = blockIdx.x;
    int k = threadIdx.x;               // 0..319
    __shared__ float sh[H_];
    __shared__ float red[20];
    __shared__ float su[R_];

    if (k < H_) sh[k] = h_old[b*H_ + k];
    __syncthreads();

    float acc = h2h_b[k];
    const float4* wr = (const float4*)(h2h_w + k * H_);
#pragma unroll
    for (int m = 0; m < H_/4; m++) {
        float4 wv = wr[m];
        acc += wv.x*sh[4*m] + wv.y*sh[4*m+1] + wv.z*sh[4*m+2] + wv.w*sh[4*m+3];
    }
    // LN over HR
    float s = acc, s2 = acc*acc;
#pragma unroll
    for (int o = 16; o > 0; o >>= 1) {
        s  += __shfl_xor_sync(0xffffffffu, s,  o);
        s2 += __shfl_xor_sync(0xffffffffu, s2, o);
    }
    int wid = k >> 5, lane = k & 31;
    if (lane == 0) { red[wid] = s; red[10 + wid] = s2; }
    __syncthreads();
    if (wid == 0) {
        float a  = (lane < 10) ? red[lane] : 0.f;
        float b2 = (lane < 10) ? red[10 + lane] : 0.f;
#pragma unroll
        for (int o = 16; o > 0; o >>= 1) {
            a  += __shfl_xor_sync(0xffffffffu, a,  o);
            b2 += __shfl_xor_sync(0xffffffffu, b2, o);
        }
        if (lane == 0) { red[0] = a; red[10] = b2; }
    }
    __syncthreads();
    float mu  = red[0] * (1.f/HR);
    float var = red[10] * (1.f/HR) - mu*mu;
    float inv = rsqrtf(var + 1e-5f);
    float wh = (acc - mu) * inv * lng[k] + lnb[k];
    float wx = g_Wx[(t*B_ + b)*HR + k];

    if (k >= H_) su[k - H_] = fmaxf(wx + wh, 0.f);
    __syncthreads();

    if (k < H_) {
        float sv = g_sv[k];
        float dv = wx + wh + g_z[b*H_ + k];
        float vo = v[b*H_ + k];
        float vn = vo + sv * (dv - vo);
        v[b*H_ + k] = vn;
        float nh = fmaxf(vn, 0.f);
        h_new[b*H_ + k] = nh;
        out_seq[(t*B_ + b)*H_ + k] = nh;
        float teo = te_old[b*H_ + k];
        te_new[b*H_ + k] = teo + sv * (sh[k] - teo);
        // mod[b,k] = sum_r mod2h[k,r] * su[r]
        float m2 = 0.f;
        const float4* mr = (const float4*)(mod2h + k * R_);
#pragma unroll
        for (int r = 0; r < R_/4; r++) {
            float4 mv = mr[r];
            m2 += mv.x*su[4*r] + mv.y*su[4*r+1] + mv.z*su[4*r+2] + mv.w*su[4*r+3];
        }
        g_mod[b*H_ + k] = m2;
    }
}

// -------- per-step big kernel: tE + dU in-place update + next-step einsum --------
// grid = (8 b-groups, H) ; block = H threads (thread = j)
__global__ void k_step_big(float* __restrict__ dU, float* __restrict__ tE,
                           const float* __restrict__ h_old,
                           const float* __restrict__ te_old,
                           const float* __restrict__ h_new,
                           const float* __restrict__ te_new) {
    int i  = blockIdx.y;
    int b0 = blockIdx.x * 8;
    int j  = threadIdx.x;
    int ij = i*H_ + j;
    float ra = g_ra[ij], sE = g_sE[ij], sU = g_sU[ij];
    float hi = g_hi[ij], lo = g_lo[ij];
    float part[8];
#pragma unroll
    for (int bb = 0; bb < 8; bb++) {
        int b = b0 + bb;
        int idx = (b*H_ + i)*H_ + j;
        float tEo   = tE[idx];
        float dUo   = dU[idx];
        float te_bj = te_old[b*H_ + j];
        float h_bj  = h_old [b*H_ + j];
        float hn_bj = h_new [b*H_ + j];
        float nh_bi  = h_new [b*H_ + i];
        float nte_bi = te_new[b*H_ + i];
        float mod_bi = g_mod [b*H_ + i];
        float tEn = tEo + sE * (nh_bi*te_bj - nte_bi*h_bj - tEo);
        float dUn = dUo + sU * (mod_bi*tEn - dUo);
        dUn = fmaxf(fminf(dUn, hi), lo);
        tE[idx] = tEn;
        dU[idx] = dUn;
        part[bb] = ra * dUn * hn_bj;   // einsum partial for next step (h = nh)
    }
    __shared__ float sp[8][H_];
#pragma unroll
    for (int bb = 0; bb < 8; bb++) sp[bb][j] = part[bb];
    __syncthreads();
    int wid = j >> 5, lane = j & 31;
    float s = 0.f;
#pragma unroll
    for (int m = 0; m < 8; m++) s += sp[wid][lane + 32*m];
#pragma unroll
    for (int o = 16; o > 0; o >>= 1) s += __shfl_xor_sync(0xffffffffu, s, o);
    if (lane == 0) g_z[(b0 + wid)*H_ + i] = s;
}

extern "C" void kernel_launch(void* const* d_in, const int* in_sizes, int n_in,
                              void* d_out, int out_size) {
    const float* x      = (const float*)d_in[0];
    const float* h0     = (const float*)d_in[1];
    const float* v0     = (const float*)d_in[2];
    const float* dU0    = (const float*)d_in[3];
    const float* te0    = (const float*)d_in[4];
    const float* tE0    = (const float*)d_in[5];
    const float* x2h_w  = (const float*)d_in[6];
    const float* x2h_b  = (const float*)d_in[7];
    const float* h2h_w  = (const float*)d_in[8];
    const float* h2h_b  = (const float*)d_in[9];
    const float* lnx_g  = (const float*)d_in[10];
    const float* lnx_b  = (const float*)d_in[11];
    const float* lnh_g  = (const float*)d_in[12];
    const float* lnh_b  = (const float*)d_in[13];
    const float* alpha  = (const float*)d_in[14];
    const float* mod2h  = (const float*)d_in[15];
    const float* tau_v  = (const float*)d_in[16];
    const float* tau_U  = (const float*)d_in[17];
    const float* tau_E  = (const float*)d_in[18];

    float* outp = (float*)d_out;
    float* o_v   = outp;                 // (B,H)
    float* o_h   = outp + 16384;         // (B,H)
    float* o_dU  = outp + 32768;         // (B,H,H)
    float* o_te  = outp + 4227072;       // (B,H)
    float* o_tE  = outp + 4243456;       // (B,H,H)
    float* o_out = outp + 8437760;       // (T,B,H)

    float* p_h;  cudaGetSymbolAddress((void**)&p_h,  g_h);
    float* p_te; cudaGetSymbolAddress((void**)&p_te, g_te);

    // working state: v, dU, tE live directly in d_out; h/te ping-pong in scratch
    cudaMemcpyAsync(o_v,  v0,  (size_t)B_*H_*sizeof(float),        cudaMemcpyDeviceToDevice, 0);
    cudaMemcpyAsync(o_dU, dU0, (size_t)B_*H_*H_*sizeof(float),     cudaMemcpyDeviceToDevice, 0);
    cudaMemcpyAsync(o_tE, tE0, (size_t)B_*H_*H_*sizeof(float),     cudaMemcpyDeviceToDevice, 0);
    cudaMemcpyAsync(p_h,  h0,  (size_t)B_*H_*sizeof(float),        cudaMemcpyDeviceToDevice, 0);
    cudaMemcpyAsync(p_te, te0, (size_t)B_*H_*sizeof(float),        cudaMemcpyDeviceToDevice, 0);

    k_consts<<<(HH + 255)/256, 256>>>(alpha, tau_U, tau_E, h2h_w, tau_v);
    k_wx<<<T_*B_, HR>>>(x, x2h_w, x2h_b, lnx_g, lnx_b);
    k_zinit<<<dim3(8, H_), H_>>>(dU0, h0);

    for (int t = 0; t < T_; t++) {
        float* h_old  = p_h  + (t & 1) * B_*H_;
        float* h_new  = p_h  + ((t + 1) & 1) * B_*H_;
        float* te_old = p_te + (t & 1) * B_*H_;
        float* te_new = p_te + ((t + 1) & 1) * B_*H_;
        k_step_small<<<B_, HR>>>(t, h_old, te_old, h_new, te_new,
                                 h2h_w, h2h_b, lnh_g, lnh_b, mod2h, o_v, o_out);
        k_step_big<<<dim3(8, H_), H_>>>(o_dU, o_tE, h_old, te_old, h_new, te_new);
    }
    // final h, te (T even -> buffer 0)
    cudaMemcpyAsync(o_h,  p_h,  (size_t)B_*H_*sizeof(float), cudaMemcpyDeviceToDevice, 0);
    cudaMemcpyAsync(o_te, p_te, (size_t)B_*H_*sizeof(float), cudaMemcpyDeviceToDevice, 0);
}